// round 4
// baseline (speedup 1.0000x reference)
#include <cuda_runtime.h>
#include <cuda_bf16.h>

// ---------------------------------------------------------------------------
// Policy_LSTM: 2-layer LSTM (B=512, T=1024, H=256, F_IN=10) + MLP head + softmax
//
// Round 3: cluster-of-2 unit-split. 64 clusters x 2 CTAs; each cluster owns 8
// batch rows; each CTA owns 128 hidden units and streams only HALF the bf16
// weights (chip L2 traffic halved vs R2). h1/h2 exchanged via DSMEM stores into
// the peer's double-buffered SMEM; 2 cluster barriers per step, one hidden
// behind the W_hh1 k-loop, one behind next-step x staging. Per-CTA partial
// advantage scores summed in the softmax kernel (no 3rd barrier).
// ---------------------------------------------------------------------------

#define BB 512
#define TT 1024

// ----- device scratch (static, allocation-free) -----
__device__ __align__(16) unsigned short g_Wbf0h[256 * 1024]; // [k<256][j][q] bf16, w_hh0
__device__ __align__(16) unsigned short g_Wbf1[512 * 1024];  // [k<512][j][q] bf16, [w_ih1; w_hh1]
__device__ __align__(16) float g_Wt0x[10 * 1024];            // [k<10][j][q] fp32, w_ih0
__device__ __align__(16) float g_b0[1024];                   // [j][q] b_ih0+b_hh0
__device__ __align__(16) float g_b1[1024];                   // [j][q] b_ih1+b_hh1
__device__ __align__(16) unsigned short g_advW1bf[256 * 256];// [k][j] bf16 of adv_w1[j][k]
__device__ float g_part[2][BB * TT];                         // per-rank partial scores, time-major

// ----- packed f32x2 helpers -----
typedef unsigned long long u64;

__device__ __forceinline__ u64 pk2(float lo, float hi) {
    u64 r;
    asm("mov.b64 %0, {%1, %2};" : "=l"(r) : "f"(lo), "f"(hi));
    return r;
}
__device__ __forceinline__ void upk2(u64 v, float& lo, float& hi) {
    asm("mov.b64 {%0, %1}, %2;" : "=f"(lo), "=f"(hi) : "l"(v));
}
__device__ __forceinline__ u64 ffma2(u64 a, u64 b, u64 c) {
    u64 d;
    asm("fma.rn.f32x2 %0, %1, %2, %3;" : "=l"(d) : "l"(a), "l"(b), "l"(c));
    return d;
}
__device__ __forceinline__ u64 dup2u(unsigned f) {
    u64 r;
    asm("mov.b64 %0, {%1, %1};" : "=l"(r) : "r"(f));
    return r;
}
__device__ __forceinline__ u64 dup2f(float f) {
    u64 r;
    asm("mov.b64 %0, {%1, %1};" : "=l"(r) : "f"(f));
    return r;
}

// ----- cluster / DSMEM helpers -----
__device__ __forceinline__ unsigned smem_u32(const void* p) {
    return (unsigned)__cvta_generic_to_shared(p);
}
__device__ __forceinline__ unsigned mapa_rank(unsigned addr, unsigned rank) {
    unsigned r;
    asm("mapa.shared::cluster.u32 %0, %1, %2;" : "=r"(r) : "r"(addr), "r"(rank));
    return r;
}
__device__ __forceinline__ void st_cluster_2x64(unsigned addr, u64 a, u64 b) {
    asm volatile("st.shared::cluster.b64 [%0], %1;"   :: "r"(addr), "l"(a) : "memory");
    asm volatile("st.shared::cluster.b64 [%0+8], %1;" :: "r"(addr), "l"(b) : "memory");
}
#define CLU_ARRIVE() asm volatile("barrier.cluster.arrive.aligned;" ::: "memory")
#define CLU_WAIT()   asm volatile("barrier.cluster.wait.aligned;"   ::: "memory")

// ----- fast activations (fp32, MUFU based, range-safe) -----
__device__ __forceinline__ float sigf(float v) {
    return __fdividef(1.0f, 1.0f + __expf(-v));
}
__device__ __forceinline__ float tanhf_(float v) {
    v = fminf(fmaxf(v, -15.0f), 15.0f);
    float e = __expf(-2.0f * v);
    return __fdividef(1.0f - e, 1.0f + e);
}

// ---------------------------------------------------------------------------
// prep: repack + bf16-quantize weights (runs every launch; deterministic)
// ---------------------------------------------------------------------------
__global__ void __launch_bounds__(256) prep_kernel(
    const float* __restrict__ w_ih0, const float* __restrict__ w_hh0,
    const float* __restrict__ b_ih0, const float* __restrict__ b_hh0,
    const float* __restrict__ w_ih1, const float* __restrict__ w_hh1,
    const float* __restrict__ b_ih1, const float* __restrict__ b_hh1,
    const float* __restrict__ adv_w1)
{
    int idx = blockIdx.x * blockDim.x + threadIdx.x;
    if (idx >= 512 * 1024) return;

    int k   = idx >> 10;
    int rem = idx & 1023;
    int j   = rem >> 2;
    int q   = rem & 3;
    int g   = q * 256 + j;

    float w1 = (k < 256) ? w_ih1[g * 256 + k] : w_hh1[g * 256 + (k - 256)];
    g_Wbf1[idx] = __bfloat16_as_ushort(__float2bfloat16(w1));

    if (idx < 256 * 1024)
        g_Wbf0h[idx] = __bfloat16_as_ushort(__float2bfloat16(w_hh0[g * 256 + k]));
    if (idx < 10 * 1024)
        g_Wt0x[idx] = w_ih0[g * 10 + k];
    if (idx < 1024) {
        g_b0[idx] = b_ih0[g] + b_hh0[g];
        g_b1[idx] = b_ih1[g] + b_hh1[g];
    }
    if (idx < 256 * 256) {
        int kk = idx >> 8;
        int o  = idx & 255;
        g_advW1bf[idx] = __bfloat16_as_ushort(__float2bfloat16(adv_w1[o * 256 + kk]));
    }
}

// ---------------------------------------------------------------------------
// main recurrence: 64 clusters x 2 CTAs x 256 threads.
// Cluster owns 8 batch rows; CTA rank r owns units j in [128r, 128r+128).
// Thread (jl = tid&127, half = tid>>7): unit j = 128r+jl, rows 4*half..4*half+3.
// h state double-buffered in SMEM, exchanged to the peer CTA via DSMEM.
// ---------------------------------------------------------------------------
__global__ void __launch_bounds__(256) __cluster_dims__(2, 1, 1) lstm_kernel(
    const float* __restrict__ x,
    const float* __restrict__ adv_b1,
    const float* __restrict__ adv_w2,
    const float* __restrict__ adv_b2)
{
    __shared__ float4 sh1[2][256][2];   // [buf][unit k][rowhalf] -> 4 rows
    __shared__ float4 sh2[2][256][2];
    __shared__ float  shx[8][12];       // x_t for 8 rows (10 used)
    __shared__ float4 sred[8];          // per-warp reduction partials

    const int tid = threadIdx.x;
    unsigned rank;
    asm("mov.u32 %0, %%cluster_ctarank;" : "=r"(rank));
    const unsigned peer = rank ^ 1u;

    const int jl   = tid & 127;
    const int half = tid >> 7;          // 0: rows 0-3, 1: rows 4-7
    const int j    = (int)rank * 128 + jl;
    const int b0   = (blockIdx.x >> 1) * 8;

    const uint2* __restrict__ Wb0h = (const uint2*)g_Wbf0h;
    const uint2* __restrict__ Wb1  = (const uint2*)g_Wbf1;
    const float4* __restrict__ Wt0x = (const float4*)g_Wt0x;
    const unsigned short* __restrict__ AdvW = g_advW1bf;

    const float4 bias0 = ((const float4*)g_b0)[j];   // (i,f,g,o)
    const float4 bias1 = ((const float4*)g_b1)[j];
    const float  hb  = adv_b1[j];
    const float  w2  = adv_w2[j];
    const float  ab2 = adv_b2[0];

    // remote (peer) addresses for my h store slots, both buffers
    unsigned rh1[2], rh2[2];
    rh1[0] = mapa_rank(smem_u32(&sh1[0][j][half]), peer);
    rh1[1] = mapa_rank(smem_u32(&sh1[1][j][half]), peer);
    rh2[0] = mapa_rank(smem_u32(&sh2[0][j][half]), peer);
    rh2[1] = mapa_rank(smem_u32(&sh2[1][j][half]), peer);

    float c1[4] = {0.f, 0.f, 0.f, 0.f};
    float c2[4] = {0.f, 0.f, 0.f, 0.f};

    // zero buffer 1 (read at t=0); stage x for t=0
    for (int i = tid; i < 512; i += 256) {
        sh1[1][i >> 1][i & 1] = make_float4(0.f, 0.f, 0.f, 0.f);
        sh2[1][i >> 1][i & 1] = make_float4(0.f, 0.f, 0.f, 0.f);
    }
    if (tid < 80) {
        int r = tid / 10, cc = tid - r * 10;
        shx[r][cc] = x[(size_t)(b0 + r) * (TT * 10) + cc];
    }
    __syncthreads();

    for (int t = 0; t < TT; t++) {
        const int bp = t & 1;       // write buffer
        const int rd = bp ^ 1;      // read buffer (prev step)

        // ---------------- cell 0: gates = b0 + h1 W_hh0^T + x W_ih0^T ------
        u64 aI01, aI23, aF01, aF23, aG01, aG23, aO01, aO23;
        aI01 = aI23 = dup2f(bias0.x);
        aF01 = aF23 = dup2f(bias0.y);
        aG01 = aG23 = dup2f(bias0.z);
        aO01 = aO23 = dup2f(bias0.w);

        #pragma unroll 8
        for (int k = 0; k < 256; k++) {
            uint2 wb = Wb0h[(k << 8) + j];
            ulonglong2 h = *(const ulonglong2*)&sh1[rd][k][half];
            u64 wi = dup2u(wb.x << 16);
            u64 wf = dup2u(wb.x & 0xffff0000u);
            u64 wg = dup2u(wb.y << 16);
            u64 wo = dup2u(wb.y & 0xffff0000u);
            aI01 = ffma2(wi, h.x, aI01); aI23 = ffma2(wi, h.y, aI23);
            aF01 = ffma2(wf, h.x, aF01); aF23 = ffma2(wf, h.y, aF23);
            aG01 = ffma2(wg, h.x, aG01); aG23 = ffma2(wg, h.y, aG23);
            aO01 = ffma2(wo, h.x, aO01); aO23 = ffma2(wo, h.y, aO23);
        }
        __syncthreads();   // shx (staged last step) visible; sred reuse safe

        const int r0 = half * 4;
        #pragma unroll
        for (int k = 0; k < 10; k++) {
            float4 w4 = Wt0x[(k << 8) + j];
            u64 x01 = pk2(shx[r0 + 0][k], shx[r0 + 1][k]);
            u64 x23 = pk2(shx[r0 + 2][k], shx[r0 + 3][k]);
            u64 wi = dup2f(w4.x), wf = dup2f(w4.y);
            u64 wg = dup2f(w4.z), wo = dup2f(w4.w);
            aI01 = ffma2(wi, x01, aI01); aI23 = ffma2(wi, x23, aI23);
            aF01 = ffma2(wf, x01, aF01); aF23 = ffma2(wf, x23, aF23);
            aG01 = ffma2(wg, x01, aG01); aG23 = ffma2(wg, x23, aG23);
            aO01 = ffma2(wo, x01, aO01); aO23 = ffma2(wo, x23, aO23);
        }

        u64 hp01, hp23;
        {
            float gi[4], gf[4], gg[4], go[4], hv[4];
            upk2(aI01, gi[0], gi[1]); upk2(aI23, gi[2], gi[3]);
            upk2(aF01, gf[0], gf[1]); upk2(aF23, gf[2], gf[3]);
            upk2(aG01, gg[0], gg[1]); upk2(aG23, gg[2], gg[3]);
            upk2(aO01, go[0], go[1]); upk2(aO23, go[2], go[3]);
            #pragma unroll
            for (int r = 0; r < 4; r++) {
                float cn = sigf(gf[r]) * c1[r] + sigf(gi[r]) * tanhf_(gg[r]);
                c1[r] = cn;
                hv[r] = sigf(go[r]) * tanhf_(cn);
            }
            hp01 = pk2(hv[0], hv[1]);
            hp23 = pk2(hv[2], hv[3]);
        }
        { ulonglong2 hh; hh.x = hp01; hh.y = hp23;
          *(ulonglong2*)&sh1[bp][j][half] = hh; }
        st_cluster_2x64(rh1[bp], hp01, hp23);
        CLU_ARRIVE();       // barrier #1 (h1 exchange) — hidden behind hh1 loop

        // ---------------- cell 1 part A: h2 W_hh1^T (old h2, no dep on #1) --
        aI01 = aI23 = dup2f(bias1.x);
        aF01 = aF23 = dup2f(bias1.y);
        aG01 = aG23 = dup2f(bias1.z);
        aO01 = aO23 = dup2f(bias1.w);

        #pragma unroll 8
        for (int k = 0; k < 256; k++) {
            uint2 wb = Wb1[((k + 256) << 8) + j];
            ulonglong2 h = *(const ulonglong2*)&sh2[rd][k][half];
            u64 wi = dup2u(wb.x << 16);
            u64 wf = dup2u(wb.x & 0xffff0000u);
            u64 wg = dup2u(wb.y << 16);
            u64 wo = dup2u(wb.y & 0xffff0000u);
            aI01 = ffma2(wi, h.x, aI01); aI23 = ffma2(wi, h.y, aI23);
            aF01 = ffma2(wf, h.x, aF01); aF23 = ffma2(wf, h.y, aF23);
            aG01 = ffma2(wg, h.x, aG01); aG23 = ffma2(wg, h.y, aG23);
            aO01 = ffma2(wo, h.x, aO01); aO23 = ffma2(wo, h.y, aO23);
        }
        CLU_WAIT();         // new h1 (both halves of units) now visible

        // ---------------- cell 1 part B: h1 W_ih1^T (new h1) ----------------
        #pragma unroll 8
        for (int k = 0; k < 256; k++) {
            uint2 wb = Wb1[(k << 8) + j];
            ulonglong2 h = *(const ulonglong2*)&sh1[bp][k][half];
            u64 wi = dup2u(wb.x << 16);
            u64 wf = dup2u(wb.x & 0xffff0000u);
            u64 wg = dup2u(wb.y << 16);
            u64 wo = dup2u(wb.y & 0xffff0000u);
            aI01 = ffma2(wi, h.x, aI01); aI23 = ffma2(wi, h.y, aI23);
            aF01 = ffma2(wf, h.x, aF01); aF23 = ffma2(wf, h.y, aF23);
            aG01 = ffma2(wg, h.x, aG01); aG23 = ffma2(wg, h.y, aG23);
            aO01 = ffma2(wo, h.x, aO01); aO23 = ffma2(wo, h.y, aO23);
        }

        {
            float gi[4], gf[4], gg[4], go[4], hv[4];
            upk2(aI01, gi[0], gi[1]); upk2(aI23, gi[2], gi[3]);
            upk2(aF01, gf[0], gf[1]); upk2(aF23, gf[2], gf[3]);
            upk2(aG01, gg[0], gg[1]); upk2(aG23, gg[2], gg[3]);
            upk2(aO01, go[0], go[1]); upk2(aO23, go[2], go[3]);
            #pragma unroll
            for (int r = 0; r < 4; r++) {
                float cn = sigf(gf[r]) * c2[r] + sigf(gi[r]) * tanhf_(gg[r]);
                c2[r] = cn;
                hv[r] = sigf(go[r]) * tanhf_(cn);
            }
            hp01 = pk2(hv[0], hv[1]);
            hp23 = pk2(hv[2], hv[3]);
        }
        { ulonglong2 hh; hh.x = hp01; hh.y = hp23;
          *(ulonglong2*)&sh2[bp][j][half] = hh; }
        st_cluster_2x64(rh2[bp], hp01, hp23);
        CLU_ARRIVE();       // barrier #2 (h2 exchange) — hidden behind x staging

        // stage x for next step while peers catch up (visible via next
        // iteration's __syncthreads after cell0)
        if (tid < 80) {
            int r = tid / 10, cc = tid - r * 10;
            int tn = (t + 1) & (TT - 1);
            shx[r][cc] = x[(size_t)(b0 + r) * (TT * 10) + tn * 10 + cc];
        }
        CLU_WAIT();         // new h2 visible

        // ---------------- advantage head (partial over this CTA's units) ---
        u64 ah01 = dup2f(hb);
        u64 ah23 = dup2f(hb);
        #pragma unroll 8
        for (int k = 0; k < 256; k++) {
            unsigned u = AdvW[(k << 8) + j];
            ulonglong2 h = *(const ulonglong2*)&sh2[bp][k][half];
            u64 wp = dup2u(u << 16);
            ah01 = ffma2(wp, h.x, ah01);
            ah23 = ffma2(wp, h.y, ah23);
        }
        float hv0, hv1, hv2, hv3;
        upk2(ah01, hv0, hv1);
        upk2(ah23, hv2, hv3);
        float4 part;
        part.x = fmaxf(hv0, 0.f) * w2;
        part.y = fmaxf(hv1, 0.f) * w2;
        part.z = fmaxf(hv2, 0.f) * w2;
        part.w = fmaxf(hv3, 0.f) * w2;

        #pragma unroll
        for (int off = 16; off > 0; off >>= 1) {
            part.x += __shfl_down_sync(0xffffffffu, part.x, off);
            part.y += __shfl_down_sync(0xffffffffu, part.y, off);
            part.z += __shfl_down_sync(0xffffffffu, part.z, off);
            part.w += __shfl_down_sync(0xffffffffu, part.w, off);
        }
        if ((tid & 31) == 0) sred[tid >> 5] = part;
        __syncthreads();
        if (tid < 8) {
            // rows 0-3 from warps 0-3 (half 0), rows 4-7 from warps 4-7
            int q = tid & 3, base = tid & 4;
            float s = ((const float*)&sred[base + 0])[q]
                    + ((const float*)&sred[base + 1])[q]
                    + ((const float*)&sred[base + 2])[q]
                    + ((const float*)&sred[base + 3])[q];
            if (rank == 0) s += ab2;
            g_part[rank][t * BB + b0 + tid] = s;   // time-major
        }
        // no trailing barrier: sred rewrite at t+1 happens after CLU_WAIT #2,
        // which orders it after this read.
    }
}

// ---------------------------------------------------------------------------
// softmax over mixed view: row i = sum of partials [i*1024 .. i*1024+1023]
// ---------------------------------------------------------------------------
__global__ void __launch_bounds__(256) softmax_kernel(float* __restrict__ out)
{
    __shared__ float sm_m[8];
    __shared__ float sm_s[8];
    const int row = blockIdx.x;
    const int tid = threadIdx.x;
    const float* ra = g_part[0] + (size_t)row * 1024;
    const float* rb = g_part[1] + (size_t)row * 1024;

    float v0 = ra[tid]       + rb[tid];
    float v1 = ra[tid + 256] + rb[tid + 256];
    float v2 = ra[tid + 512] + rb[tid + 512];
    float v3 = ra[tid + 768] + rb[tid + 768];

    float m = fmaxf(fmaxf(v0, v1), fmaxf(v2, v3));
    #pragma unroll
    for (int off = 16; off > 0; off >>= 1)
        m = fmaxf(m, __shfl_xor_sync(0xffffffffu, m, off));
    if ((tid & 31) == 0) sm_m[tid >> 5] = m;
    __syncthreads();
    float bm = sm_m[0];
    #pragma unroll
    for (int w = 1; w < 8; w++) bm = fmaxf(bm, sm_m[w]);

    float e0 = __expf(v0 - bm), e1 = __expf(v1 - bm);
    float e2 = __expf(v2 - bm), e3 = __expf(v3 - bm);
    float s = e0 + e1 + e2 + e3;
    #pragma unroll
    for (int off = 16; off > 0; off >>= 1)
        s += __shfl_xor_sync(0xffffffffu, s, off);
    if ((tid & 31) == 0) sm_s[tid >> 5] = s;
    __syncthreads();
    float S = 0.f;
    #pragma unroll
    for (int w = 0; w < 8; w++) S += sm_s[w];
    float inv = __fdividef(1.0f, S);

    float* op = out + (size_t)row * 1024;
    op[tid]       = e0 * inv;
    op[tid + 256] = e1 * inv;
    op[tid + 512] = e2 * inv;
    op[tid + 768] = e3 * inv;
}

// ---------------------------------------------------------------------------
extern "C" void kernel_launch(void* const* d_in, const int* in_sizes, int n_in,
                              void* d_out, int out_size)
{
    const float* x      = (const float*)d_in[0];
    const float* w_ih0  = (const float*)d_in[1];
    const float* w_hh0  = (const float*)d_in[2];
    const float* b_ih0  = (const float*)d_in[3];
    const float* b_hh0  = (const float*)d_in[4];
    const float* w_ih1  = (const float*)d_in[5];
    const float* w_hh1  = (const float*)d_in[6];
    const float* b_ih1  = (const float*)d_in[7];
    const float* b_hh1  = (const float*)d_in[8];
    const float* adv_w1 = (const float*)d_in[9];
    const float* adv_b1 = (const float*)d_in[10];
    const float* adv_w2 = (const float*)d_in[11];
    const float* adv_b2 = (const float*)d_in[12];
    float* out = (float*)d_out;

    prep_kernel<<<2048, 256>>>(w_ih0, w_hh0, b_ih0, b_hh0,
                               w_ih1, w_hh1, b_ih1, b_hh1, adv_w1);
    lstm_kernel<<<128, 256>>>(x, adv_b1, adv_w2, adv_b2);   // cluster dims (2,1,1) via attribute
    softmax_kernel<<<512, 256>>>(out);
}

// round 9
// speedup vs baseline: 1.7263x; 1.7263x over previous
#include <cuda_runtime.h>
#include <cuda_bf16.h>

// ---------------------------------------------------------------------------
// Policy_LSTM: 2-layer LSTM (B=512, T=1024, H=256, F_IN=10) + MLP head + softmax
//
// Round 4: revert cluster (R3 regression). Keep R2 compute structure, but feed
// the bf16 weight stream through a 3-stage x 64KB SMEM ring filled by a
// dedicated producer warp with cp.async.bulk + mbarriers. Compute warps read
// weights from SMEM (no in-loop LDG latency). Compute-warp-only named barrier.
// ---------------------------------------------------------------------------

#define BB 512
#define TT 1024
#define NSTAGE 3
#define CHUNK_BYTES 65536
#define CHUNKS_PER_STEP 26
#define STREAM_USHORTS 851968   // 26 * 32768

// ----- device scratch (static, allocation-free) -----
// stream layout (ushort bf16):
//   [0,       262144): W_hh0   idx = k*1024 + j*4 + q            (chunks 0-7)
//   [262144,  524288): W_ih1   idx = 262144 + k*1024 + j*4 + q   (chunks 8-15)
//   [524288,  786432): W_hh1   idx = 524288 + k*1024 + j*4 + q   (chunks 16-23)
//   [786432,  851968): advW1^T idx = 786432 + k*256 + j          (chunks 24-25)
__device__ __align__(16) unsigned short g_stream[STREAM_USHORTS];
__device__ __align__(16) float g_Wt0x[10 * 1024];   // [k<10][j][q] fp32 w_ih0
__device__ __align__(16) float g_b0[1024];          // [j][q] b_ih0+b_hh0
__device__ __align__(16) float g_b1[1024];          // [j][q] b_ih1+b_hh1
__device__ float g_scores[BB * TT];                 // time-major: idx = t*B + b

// ----- packed f32x2 helpers -----
typedef unsigned long long u64;

__device__ __forceinline__ u64 pk2(float lo, float hi) {
    u64 r;
    asm("mov.b64 %0, {%1, %2};" : "=l"(r) : "f"(lo), "f"(hi));
    return r;
}
__device__ __forceinline__ void upk2(u64 v, float& lo, float& hi) {
    asm("mov.b64 {%0, %1}, %2;" : "=f"(lo), "=f"(hi) : "l"(v));
}
__device__ __forceinline__ u64 ffma2(u64 a, u64 b, u64 c) {
    u64 d;
    asm("fma.rn.f32x2 %0, %1, %2, %3;" : "=l"(d) : "l"(a), "l"(b), "l"(c));
    return d;
}
__device__ __forceinline__ u64 dup2u(unsigned f) {
    u64 r;
    asm("mov.b64 %0, {%1, %1};" : "=l"(r) : "r"(f));
    return r;
}
__device__ __forceinline__ u64 dup2f(float f) {
    u64 r;
    asm("mov.b64 %0, {%1, %1};" : "=l"(r) : "f"(f));
    return r;
}

// ----- mbarrier / bulk-copy helpers -----
__device__ __forceinline__ unsigned smem_u32(const void* p) {
    return (unsigned)__cvta_generic_to_shared(p);
}
__device__ __forceinline__ void mbar_init(unsigned a, unsigned cnt) {
    asm volatile("mbarrier.init.shared.b64 [%0], %1;" :: "r"(a), "r"(cnt) : "memory");
}
__device__ __forceinline__ void mbar_expect_tx(unsigned a, unsigned tx) {
    asm volatile("mbarrier.arrive.expect_tx.shared.b64 _, [%0], %1;" :: "r"(a), "r"(tx) : "memory");
}
__device__ __forceinline__ void mbar_arrive(unsigned a) {
    asm volatile("mbarrier.arrive.shared.b64 _, [%0];" :: "r"(a) : "memory");
}
__device__ __forceinline__ void mbar_wait_acq(unsigned a, unsigned ph) {
    asm volatile(
        "{\n\t.reg .pred P;\n"
        "LW%=:\n\t"
        "mbarrier.try_wait.parity.acquire.cta.shared::cta.b64 P, [%0], %1, 0x989680;\n\t"
        "@!P bra LW%=;\n\t"
        "}" :: "r"(a), "r"(ph) : "memory");
}
__device__ __forceinline__ void mbar_wait_rlx(unsigned a, unsigned ph) {
    asm volatile(
        "{\n\t.reg .pred P;\n"
        "LW%=:\n\t"
        "mbarrier.try_wait.parity.relaxed.cta.shared::cta.b64 P, [%0], %1, 0x989680;\n\t"
        "@!P bra LW%=;\n\t"
        "}" :: "r"(a), "r"(ph) : "memory");
}
__device__ __forceinline__ void bulk_cp(unsigned dst, const void* src, unsigned bytes, unsigned mbar) {
    asm volatile(
        "cp.async.bulk.shared::cluster.global.mbarrier::complete_tx::bytes [%0], [%1], %2, [%3];"
        :: "r"(dst), "l"(src), "r"(bytes), "r"(mbar) : "memory");
}
#define BAR1() asm volatile("bar.sync 1, 256;" ::: "memory")
#define CUR_NEXT(st, ph) do { if (++(st) == NSTAGE) { (st) = 0; (ph) ^= 1; } } while (0)

// ----- fast activations (fp32, MUFU based, range-safe) -----
__device__ __forceinline__ float sigf(float v) {
    return __fdividef(1.0f, 1.0f + __expf(-v));
}
__device__ __forceinline__ float tanhf_(float v) {
    v = fminf(fmaxf(v, -15.0f), 15.0f);
    float e = __expf(-2.0f * v);
    return __fdividef(1.0f - e, 1.0f + e);
}

// ---------------------------------------------------------------------------
// prep: repack + bf16-quantize weights into the stream (every launch)
// ---------------------------------------------------------------------------
__global__ void __launch_bounds__(256) prep_kernel(
    const float* __restrict__ w_ih0, const float* __restrict__ w_hh0,
    const float* __restrict__ b_ih0, const float* __restrict__ b_hh0,
    const float* __restrict__ w_ih1, const float* __restrict__ w_hh1,
    const float* __restrict__ b_ih1, const float* __restrict__ b_hh1,
    const float* __restrict__ adv_w1)
{
    int idx = blockIdx.x * blockDim.x + threadIdx.x;   // grid covers 851968
    if (idx >= STREAM_USHORTS) return;

    if (idx < 786432) {
        int sec = idx >> 18;            // 0: w_hh0, 1: w_ih1, 2: w_hh1
        int k   = (idx >> 10) & 255;
        int j   = (idx >> 2) & 255;
        int q   = idx & 3;
        int g   = q * 256 + j;
        float v = (sec == 0) ? w_hh0[g * 256 + k]
                : (sec == 1) ? w_ih1[g * 256 + k]
                             : w_hh1[g * 256 + k];
        g_stream[idx] = __bfloat16_as_ushort(__float2bfloat16(v));
    } else {
        int a = idx - 786432;
        int k = a >> 8, j = a & 255;
        g_stream[idx] = __bfloat16_as_ushort(__float2bfloat16(adv_w1[j * 256 + k]));
    }

    if (idx < 10 * 1024) {
        int k = idx >> 10, jq = idx & 1023;
        int j = jq >> 2, q = jq & 3, g = q * 256 + j;
        g_Wt0x[idx] = w_ih0[g * 10 + k];
    }
    if (idx < 1024) {
        int j = idx >> 2, q = idx & 3, g = q * 256 + j;
        g_b0[idx] = b_ih0[g] + b_hh0[g];
        g_b1[idx] = b_ih1[g] + b_hh1[g];
    }
}

// ---------------------------------------------------------------------------
// main recurrence: 128 CTAs x 288 threads (8 compute warps + 1 producer warp),
// 4 batch rows per CTA, thread j < 256 owns hidden unit j.
// ---------------------------------------------------------------------------
__global__ void __launch_bounds__(288) lstm_kernel(
    const float* __restrict__ x,
    const float* __restrict__ adv_b1,
    const float* __restrict__ adv_w2,
    const float* __restrict__ adv_b2)
{
    extern __shared__ __align__(16) char ringbuf[];   // NSTAGE * 64KB

    __shared__ float4 sh1[256];     // h1: [unit k] -> 4 batch rows
    __shared__ float4 sh2[256];     // h2
    __shared__ float  shx[4][12];   // x_t per batch row (10 used)
    __shared__ float4 sred[8];      // per-warp reduction partials
    __shared__ __align__(8) unsigned long long s_mbar[2 * NSTAGE]; // [0..2] full, [3..5] empty

    const int tid = threadIdx.x;
    const int b0  = blockIdx.x * 4;

    unsigned mb_full[NSTAGE], mb_empty[NSTAGE], ring_u32[NSTAGE];
    #pragma unroll
    for (int s = 0; s < NSTAGE; s++) {
        mb_full[s]  = smem_u32(&s_mbar[s]);
        mb_empty[s] = smem_u32(&s_mbar[NSTAGE + s]);
        ring_u32[s] = smem_u32(ringbuf + s * CHUNK_BYTES);
    }

    if (tid == 0) {
        #pragma unroll
        for (int s = 0; s < NSTAGE; s++) {
            mbar_init(mb_full[s], 1);    // completed by expect_tx + bulk tx
            mbar_init(mb_empty[s], 8);   // one arrive per compute warp
        }
    }
    if (tid < 256) {
        sh1[tid] = make_float4(0.f, 0.f, 0.f, 0.f);
        sh2[tid] = make_float4(0.f, 0.f, 0.f, 0.f);
    }
    __syncthreads();   // only block-wide barrier; covers mbar init + sh zero

    // ======================= producer warp (tid >= 256) ====================
    if (tid >= 256) {
        const char* src = (const char*)g_stream;
        int pst = 0, pph = 1;           // producer phase starts flipped
        for (int t = 0; t < TT; t++) {
            for (int c = 0; c < CHUNKS_PER_STEP; c++) {
                mbar_wait_rlx(mb_empty[pst], pph);
                if ((tid & 31) == 0) {
                    mbar_expect_tx(mb_full[pst], CHUNK_BYTES);
                    bulk_cp(ring_u32[pst], src + (size_t)c * CHUNK_BYTES,
                            CHUNK_BYTES, mb_full[pst]);
                }
                CUR_NEXT(pst, pph);
            }
        }
        return;
    }

    // ======================= compute warps (tid < 256) =====================
    const int j = tid;
    const float4* __restrict__ Wt0x = (const float4*)g_Wt0x;

    const float4 bias0 = ((const float4*)g_b0)[j];   // (i,f,g,o)
    const float4 bias1 = ((const float4*)g_b1)[j];
    const float  hb  = adv_b1[j];
    const float  w2  = adv_w2[j];
    const float  ab2 = adv_b2[0];

    float c1[4] = {0.f, 0.f, 0.f, 0.f};
    float c2[4] = {0.f, 0.f, 0.f, 0.f};

    int cst = 0, cph = 0;               // consumer ring cursor

    for (int t = 0; t < TT; t++) {
        // stage x_t for this CTA's 4 batch rows
        if (j < 40) {
            int r = j / 10, cc = j - r * 10;
            shx[r][cc] = x[(size_t)(b0 + r) * (TT * 10) + t * 10 + cc];
        }

        // ---------------- cell 0: gates = b0 + h1 W_hh0^T + x W_ih0^T ------
        u64 aI01, aI23, aF01, aF23, aG01, aG23, aO01, aO23;
        aI01 = aI23 = dup2f(bias0.x);
        aF01 = aF23 = dup2f(bias0.y);
        aG01 = aG23 = dup2f(bias0.z);
        aO01 = aO23 = dup2f(bias0.w);

        for (int c = 0; c < 8; c++) {
            mbar_wait_acq(mb_full[cst], cph);
            const uint2* __restrict__ wp =
                (const uint2*)(ringbuf + cst * CHUNK_BYTES);
            const int kg = c * 32;
            #pragma unroll 8
            for (int kl = 0; kl < 32; kl++) {
                uint2 wb = wp[(kl << 8) + j];
                ulonglong2 h = *(const ulonglong2*)&sh1[kg + kl];
                u64 wi = dup2u(wb.x << 16);
                u64 wf = dup2u(wb.x & 0xffff0000u);
                u64 wg = dup2u(wb.y << 16);
                u64 wo = dup2u(wb.y & 0xffff0000u);
                aI01 = ffma2(wi, h.x, aI01); aI23 = ffma2(wi, h.y, aI23);
                aF01 = ffma2(wf, h.x, aF01); aF23 = ffma2(wf, h.y, aF23);
                aG01 = ffma2(wg, h.x, aG01); aG23 = ffma2(wg, h.y, aG23);
                aO01 = ffma2(wo, h.x, aO01); aO23 = ffma2(wo, h.y, aO23);
            }
            if ((tid & 31) == 0) mbar_arrive(mb_empty[cst]);
            CUR_NEXT(cst, cph);
        }
        BAR1();   // shx visible; everyone done reading old sh1

        #pragma unroll
        for (int k = 0; k < 10; k++) {
            float4 w4 = Wt0x[(k << 8) + j];
            u64 x01 = pk2(shx[0][k], shx[1][k]);
            u64 x23 = pk2(shx[2][k], shx[3][k]);
            u64 wi = dup2f(w4.x), wf = dup2f(w4.y);
            u64 wg = dup2f(w4.z), wo = dup2f(w4.w);
            aI01 = ffma2(wi, x01, aI01); aI23 = ffma2(wi, x23, aI23);
            aF01 = ffma2(wf, x01, aF01); aF23 = ffma2(wf, x23, aF23);
            aG01 = ffma2(wg, x01, aG01); aG23 = ffma2(wg, x23, aG23);
            aO01 = ffma2(wo, x01, aO01); aO23 = ffma2(wo, x23, aO23);
        }

        float4 h1n;
        {
            float gi[4], gf[4], gg[4], go[4];
            upk2(aI01, gi[0], gi[1]); upk2(aI23, gi[2], gi[3]);
            upk2(aF01, gf[0], gf[1]); upk2(aF23, gf[2], gf[3]);
            upk2(aG01, gg[0], gg[1]); upk2(aG23, gg[2], gg[3]);
            upk2(aO01, go[0], go[1]); upk2(aO23, go[2], go[3]);
            float* h1p = (float*)&h1n;
            #pragma unroll
            for (int r = 0; r < 4; r++) {
                float cn = sigf(gf[r]) * c1[r] + sigf(gi[r]) * tanhf_(gg[r]);
                c1[r] = cn;
                h1p[r] = sigf(go[r]) * tanhf_(cn);
            }
        }
        sh1[j] = h1n;    // safe: all reads of old sh1 completed pre-barrier
        BAR1();          // new sh1 visible

        // ---------------- cell 1: gates = b1 + h1 W_ih1^T + h2 W_hh1^T -----
        aI01 = aI23 = dup2f(bias1.x);
        aF01 = aF23 = dup2f(bias1.y);
        aG01 = aG23 = dup2f(bias1.z);
        aO01 = aO23 = dup2f(bias1.w);

        for (int c = 0; c < 8; c++) {       // ih: new h1
            mbar_wait_acq(mb_full[cst], cph);
            const uint2* __restrict__ wp =
                (const uint2*)(ringbuf + cst * CHUNK_BYTES);
            const int kg = c * 32;
            #pragma unroll 8
            for (int kl = 0; kl < 32; kl++) {
                uint2 wb = wp[(kl << 8) + j];
                ulonglong2 h = *(const ulonglong2*)&sh1[kg + kl];
                u64 wi = dup2u(wb.x << 16);
                u64 wf = dup2u(wb.x & 0xffff0000u);
                u64 wg = dup2u(wb.y << 16);
                u64 wo = dup2u(wb.y & 0xffff0000u);
                aI01 = ffma2(wi, h.x, aI01); aI23 = ffma2(wi, h.y, aI23);
                aF01 = ffma2(wf, h.x, aF01); aF23 = ffma2(wf, h.y, aF23);
                aG01 = ffma2(wg, h.x, aG01); aG23 = ffma2(wg, h.y, aG23);
                aO01 = ffma2(wo, h.x, aO01); aO23 = ffma2(wo, h.y, aO23);
            }
            if ((tid & 31) == 0) mbar_arrive(mb_empty[cst]);
            CUR_NEXT(cst, cph);
        }
        for (int c = 0; c < 8; c++) {       // hh: old h2
            mbar_wait_acq(mb_full[cst], cph);
            const uint2* __restrict__ wp =
                (const uint2*)(ringbuf + cst * CHUNK_BYTES);
            const int kg = c * 32;
            #pragma unroll 8
            for (int kl = 0; kl < 32; kl++) {
                uint2 wb = wp[(kl << 8) + j];
                ulonglong2 h = *(const ulonglong2*)&sh2[kg + kl];
                u64 wi = dup2u(wb.x << 16);
                u64 wf = dup2u(wb.x & 0xffff0000u);
                u64 wg = dup2u(wb.y << 16);
                u64 wo = dup2u(wb.y & 0xffff0000u);
                aI01 = ffma2(wi, h.x, aI01); aI23 = ffma2(wi, h.y, aI23);
                aF01 = ffma2(wf, h.x, aF01); aF23 = ffma2(wf, h.y, aF23);
                aG01 = ffma2(wg, h.x, aG01); aG23 = ffma2(wg, h.y, aG23);
                aO01 = ffma2(wo, h.x, aO01); aO23 = ffma2(wo, h.y, aO23);
            }
            if ((tid & 31) == 0) mbar_arrive(mb_empty[cst]);
            CUR_NEXT(cst, cph);
        }
        BAR1();   // everyone done reading old sh2

        float4 h2n;
        {
            float gi[4], gf[4], gg[4], go[4];
            upk2(aI01, gi[0], gi[1]); upk2(aI23, gi[2], gi[3]);
            upk2(aF01, gf[0], gf[1]); upk2(aF23, gf[2], gf[3]);
            upk2(aG01, gg[0], gg[1]); upk2(aG23, gg[2], gg[3]);
            upk2(aO01, go[0], go[1]); upk2(aO23, go[2], go[3]);
            float* h2p = (float*)&h2n;
            #pragma unroll
            for (int r = 0; r < 4; r++) {
                float cn = sigf(gf[r]) * c2[r] + sigf(gi[r]) * tanhf_(gg[r]);
                c2[r] = cn;
                h2p[r] = sigf(go[r]) * tanhf_(cn);
            }
        }
        sh2[j] = h2n;
        BAR1();   // new sh2 visible

        // ---------------- advantage head -----------------------------------
        u64 ah01 = dup2f(hb);
        u64 ah23 = dup2f(hb);
        for (int c = 0; c < 2; c++) {
            mbar_wait_acq(mb_full[cst], cph);
            const unsigned short* __restrict__ ap =
                (const unsigned short*)(ringbuf + cst * CHUNK_BYTES);
            const int kg = c * 128;
            #pragma unroll 8
            for (int kl = 0; kl < 128; kl++) {
                unsigned u = ap[(kl << 8) + j];
                ulonglong2 h = *(const ulonglong2*)&sh2[kg + kl];
                u64 wp2 = dup2u(u << 16);
                ah01 = ffma2(wp2, h.x, ah01);
                ah23 = ffma2(wp2, h.y, ah23);
            }
            if ((tid & 31) == 0) mbar_arrive(mb_empty[cst]);
            CUR_NEXT(cst, cph);
        }
        float hv0, hv1, hv2, hv3;
        upk2(ah01, hv0, hv1);
        upk2(ah23, hv2, hv3);
        float4 part;
        part.x = fmaxf(hv0, 0.f) * w2;
        part.y = fmaxf(hv1, 0.f) * w2;
        part.z = fmaxf(hv2, 0.f) * w2;
        part.w = fmaxf(hv3, 0.f) * w2;

        #pragma unroll
        for (int off = 16; off > 0; off >>= 1) {
            part.x += __shfl_down_sync(0xffffffffu, part.x, off);
            part.y += __shfl_down_sync(0xffffffffu, part.y, off);
            part.z += __shfl_down_sync(0xffffffffu, part.z, off);
            part.w += __shfl_down_sync(0xffffffffu, part.w, off);
        }
        if ((tid & 31) == 0) sred[tid >> 5] = part;
        BAR1();
        if (tid < 4) {
            float s = ab2;
            #pragma unroll
            for (int w = 0; w < 8; w++) s += ((const float*)&sred[w])[tid];
            g_scores[t * BB + b0 + tid] = s;   // time-major flat buffer
        }
        BAR1();   // protect sred / shx reuse next step
    }
}

// ---------------------------------------------------------------------------
// softmax over mixed view: row i = g_scores[i*1024 .. i*1024+1023]
// ---------------------------------------------------------------------------
__global__ void __launch_bounds__(256) softmax_kernel(float* __restrict__ out)
{
    __shared__ float sm_m[8];
    __shared__ float sm_s[8];
    const int row = blockIdx.x;
    const int tid = threadIdx.x;
    const float* rp = g_scores + (size_t)row * 1024;

    float v0 = rp[tid], v1 = rp[tid + 256], v2 = rp[tid + 512], v3 = rp[tid + 768];

    float m = fmaxf(fmaxf(v0, v1), fmaxf(v2, v3));
    #pragma unroll
    for (int off = 16; off > 0; off >>= 1)
        m = fmaxf(m, __shfl_xor_sync(0xffffffffu, m, off));
    if ((tid & 31) == 0) sm_m[tid >> 5] = m;
    __syncthreads();
    float bm = sm_m[0];
    #pragma unroll
    for (int w = 1; w < 8; w++) bm = fmaxf(bm, sm_m[w]);

    float e0 = __expf(v0 - bm), e1 = __expf(v1 - bm);
    float e2 = __expf(v2 - bm), e3 = __expf(v3 - bm);
    float s = e0 + e1 + e2 + e3;
    #pragma unroll
    for (int off = 16; off > 0; off >>= 1)
        s += __shfl_xor_sync(0xffffffffu, s, off);
    if ((tid & 31) == 0) sm_s[tid >> 5] = s;
    __syncthreads();
    float S = 0.f;
    #pragma unroll
    for (int w = 0; w < 8; w++) S += sm_s[w];
    float inv = __fdividef(1.0f, S);

    float* op = out + (size_t)row * 1024;
    op[tid]       = e0 * inv;
    op[tid + 256] = e1 * inv;
    op[tid + 512] = e2 * inv;
    op[tid + 768] = e3 * inv;
}

// ---------------------------------------------------------------------------
extern "C" void kernel_launch(void* const* d_in, const int* in_sizes, int n_in,
                              void* d_out, int out_size)
{
    const float* x      = (const float*)d_in[0];
    const float* w_ih0  = (const float*)d_in[1];
    const float* w_hh0  = (const float*)d_in[2];
    const float* b_ih0  = (const float*)d_in[3];
    const float* b_hh0  = (const float*)d_in[4];
    const float* w_ih1  = (const float*)d_in[5];
    const float* w_hh1  = (const float*)d_in[6];
    const float* b_ih1  = (const float*)d_in[7];
    const float* b_hh1  = (const float*)d_in[8];
    const float* adv_w1 = (const float*)d_in[9];
    const float* adv_b1 = (const float*)d_in[10];
    const float* adv_w2 = (const float*)d_in[11];
    const float* adv_b2 = (const float*)d_in[12];
    float* out = (float*)d_out;

    static int smem_set = 0;
    (void)smem_set;  // attribute set is idempotent & deterministic; call every time
    cudaFuncSetAttribute(lstm_kernel,
                         cudaFuncAttributeMaxDynamicSharedMemorySize,
                         NSTAGE * CHUNK_BYTES);

    prep_kernel<<<3328, 256>>>(w_ih0, w_hh0, b_ih0, b_hh0,
                               w_ih1, w_hh1, b_ih1, b_hh1, adv_w1);
    lstm_kernel<<<128, 288, NSTAGE * CHUNK_BYTES>>>(x, adv_b1, adv_w2, adv_b2);
    softmax_kernel<<<512, 256>>>(out);
}